// round 4
// baseline (speedup 1.0000x reference)
#include <cuda_runtime.h>
#include <cuda_bf16.h>
#include <math.h>

// ---------------- problem constants ----------------
#define BB 2
#define TT 1024
#define DD 1024
#define HH 16
#define HD 64
#define LL 6
#define VV 32000
#define FF 4096          // 4*D
#define MM (BB*TT)       // 2048 rows
#define BH (BB*HH)       // 32 (b,h) pairs
#define EPS 1e-5f
#define ATT_SCALE 0.03125f   // D^-0.5 = 1/32 (source scales by n_embd)

// ---------------- scratch (static device globals; no allocs) ----------------
__device__ float g_x   [(size_t)MM*DD];
__device__ float g_x2  [(size_t)MM*DD];
__device__ float g_q   [(size_t)MM*DD];
__device__ float g_k   [(size_t)MM*DD];
__device__ float g_v   [(size_t)MM*DD];
__device__ float g_oc  [(size_t)MM*DD];
__device__ float g_h   [(size_t)MM*FF];
__device__ float g_sc  [(size_t)BH*TT*TT];      // 128 MB attention scores
__device__ float g_wt  [(size_t)LL*3*DD*DD];    // repacked Wq/Wk/Wv -> row-major [D, H*HD]
__device__ float g_nll [MM];
__device__ float g_logits_scratch[(size_t)MM*VV]; // only used if d_out can't hold logits

// ---------------- embedding ----------------
__global__ __launch_bounds__(256) void embed_kernel(
    const int* __restrict__ idx, const float* __restrict__ tok,
    const float* __restrict__ pos, float* __restrict__ x)
{
    size_t i = (size_t)blockIdx.x * 256 + threadIdx.x;
    if (i >= (size_t)MM * DD) return;
    int d = (int)(i % DD);
    int r = (int)(i / DD);
    int t = r % TT;
    x[i] = tok[(size_t)idx[r] * DD + d] + pos[(size_t)t * DD + d];
}

// ---------------- repack Wq/Wk/Wv [L,H,D,HD] -> [L,3,D, H*HD] row-major ----------------
__global__ __launch_bounds__(256) void pack_qkv_kernel(
    const float* __restrict__ Wq, const float* __restrict__ Wk,
    const float* __restrict__ Wv, float* __restrict__ wt)
{
    size_t i = (size_t)blockIdx.x * 256 + threadIdx.x;
    size_t total = (size_t)LL * 3 * DD * DD;
    if (i >= total) return;
    int e = (int)(i % HD); size_t r = i / HD;
    int d = (int)(r % DD); r /= DD;
    int h = (int)(r % HH); r /= HH;
    int m = (int)(r % 3);  int l = (int)(r / 3);
    const float* src = (m == 0) ? Wq : (m == 1) ? Wk : Wv;
    float val = src[(((size_t)l * HH + h) * DD + d) * HD + e];
    wt[(((size_t)(l * 3 + m)) * DD + d) * DD + (size_t)h * HD + e] = val;
}

// ---------------- generic 128x128x16 fp32 GEMM with fused epilogue ----------------
// C[M,N] = A[M,K] @ B[K,N] (+bias[N]) (+resid[M,N]) (relu)
// Requires M%128==0, N%128==0, K%16==0, 16B-aligned pointers. All shapes here qualify.
template<bool BIAS, bool RELU, bool RESID>
__global__ __launch_bounds__(256) void gemm128(
    const float* __restrict__ A, const float* __restrict__ Bm,
    const float* __restrict__ bias, const float* __restrict__ resid,
    float* __restrict__ C, int M, int N, int K)
{
    __shared__ float As[16][132];   // stored transposed: As[k][m]
    __shared__ float Bs[16][132];   // Bs[k][n]
    const int tid = threadIdx.x;
    const int tx = tid & 15, ty = tid >> 4;
    const int m0 = blockIdx.y * 128, n0 = blockIdx.x * 128;

    float acc[8][8];
#pragma unroll
    for (int i = 0; i < 8; i++)
#pragma unroll
        for (int j = 0; j < 8; j++) acc[i][j] = 0.f;

    for (int kk = 0; kk < K; kk += 16) {
#pragma unroll
        for (int ld = 0; ld < 2; ld++) {
            int f = tid + ld * 256;            // 512 float4 of A tile
            int row = f >> 2, c = (f & 3) << 2;
            float4 v = *(const float4*)(A + (size_t)(m0 + row) * K + kk + c);
            As[c + 0][row] = v.x; As[c + 1][row] = v.y;
            As[c + 2][row] = v.z; As[c + 3][row] = v.w;
        }
#pragma unroll
        for (int ld = 0; ld < 2; ld++) {
            int f = tid + ld * 256;            // 512 float4 of B tile
            int row = f >> 5, c = (f & 31) << 2;
            *(float4*)(&Bs[row][c]) = *(const float4*)(Bm + (size_t)(kk + row) * N + n0 + c);
        }
        __syncthreads();
#pragma unroll
        for (int k = 0; k < 16; k++) {
            float4 a0 = *(float4*)&As[k][ty * 8];
            float4 a1 = *(float4*)&As[k][ty * 8 + 4];
            float4 b0 = *(float4*)&Bs[k][tx * 8];
            float4 b1 = *(float4*)&Bs[k][tx * 8 + 4];
            float a[8] = {a0.x,a0.y,a0.z,a0.w,a1.x,a1.y,a1.z,a1.w};
            float b[8] = {b0.x,b0.y,b0.z,b0.w,b1.x,b1.y,b1.z,b1.w};
#pragma unroll
            for (int i = 0; i < 8; i++)
#pragma unroll
                for (int j = 0; j < 8; j++)
                    acc[i][j] = fmaf(a[i], b[j], acc[i][j]);
        }
        __syncthreads();
    }

#pragma unroll
    for (int i = 0; i < 8; i++) {
        int row = m0 + ty * 8 + i;
        size_t base = (size_t)row * N + n0 + tx * 8;
#pragma unroll
        for (int j = 0; j < 8; j++) {
            float v = acc[i][j];
            if (BIAS)  v += bias[n0 + tx * 8 + j];
            if (RESID) v += resid[base + j];
            if (RELU)  v = fmaxf(v, 0.f);
            C[base + j] = v;
        }
    }
}

// ---------------- attention: scores = scale * Q K^T (lower-triangular blocks only) ----------------
__global__ __launch_bounds__(256) void attn_scores_kernel(
    const float* __restrict__ q, const float* __restrict__ k, float* __restrict__ sc)
{
    const int bh = blockIdx.z;
    const int b = bh / HH, h = bh % HH;
    const int t0 = blockIdx.y * 64, s0 = blockIdx.x * 64;
    if (s0 > t0 + 63) return;   // fully masked block
    __shared__ float Qs[64][68];
    __shared__ float Ks[64][68];
    const int tid = threadIdx.x;
    const int tx = tid & 15, ty = tid >> 4;

#pragma unroll
    for (int ld = 0; ld < 4; ld++) {
        int f = tid + ld * 256;                // 1024 float4 per tile
        int row = f >> 4, c = (f & 15) << 2;
        *(float4*)&Qs[row][c] = *(const float4*)(q + (size_t)(b * TT + t0 + row) * DD + h * HD + c);
        *(float4*)&Ks[row][c] = *(const float4*)(k + (size_t)(b * TT + s0 + row) * DD + h * HD + c);
    }
    __syncthreads();

    float acc[4][4];
#pragma unroll
    for (int i = 0; i < 4; i++)
#pragma unroll
        for (int j = 0; j < 4; j++) acc[i][j] = 0.f;

#pragma unroll 4
    for (int e = 0; e < 64; e++) {
        float a[4], bb[4];
#pragma unroll
        for (int i = 0; i < 4; i++) a[i]  = Qs[ty * 4 + i][e];
#pragma unroll
        for (int j = 0; j < 4; j++) bb[j] = Ks[tx * 4 + j][e];
#pragma unroll
        for (int i = 0; i < 4; i++)
#pragma unroll
            for (int j = 0; j < 4; j++)
                acc[i][j] = fmaf(a[i], bb[j], acc[i][j]);
    }

#pragma unroll
    for (int i = 0; i < 4; i++) {
        size_t base = ((size_t)bh * TT + t0 + ty * 4 + i) * TT + s0 + tx * 4;
#pragma unroll
        for (int j = 0; j < 4; j++)
            sc[base + j] = acc[i][j] * ATT_SCALE;
    }
}

// ---------------- causal row softmax (writes zeros above diagonal) ----------------
__global__ __launch_bounds__(256) void softmax_kernel(float* __restrict__ sc)
{
    const int t = blockIdx.x, bh = blockIdx.y;
    float* row = sc + ((size_t)bh * TT + t) * TT;
    const int n = t + 1;
    const int tid = threadIdx.x;
    __shared__ float sh[256];

    float m = -INFINITY;
    for (int i = tid; i < n; i += 256) m = fmaxf(m, row[i]);
    sh[tid] = m; __syncthreads();
    for (int s = 128; s > 0; s >>= 1) { if (tid < s) sh[tid] = fmaxf(sh[tid], sh[tid + s]); __syncthreads(); }
    m = sh[0]; __syncthreads();

    float ssum = 0.f;
    for (int i = tid; i < n; i += 256) {
        float e = expf(row[i] - m);
        row[i] = e;
        ssum += e;
    }
    sh[tid] = ssum; __syncthreads();
    for (int s = 128; s > 0; s >>= 1) { if (tid < s) sh[tid] += sh[tid + s]; __syncthreads(); }
    float inv = 1.f / sh[0]; __syncthreads();

    for (int i = tid; i < TT; i += 256) {
        if (i < n) row[i] *= inv;
        else       row[i] = 0.f;
    }
}

// ---------------- O = att @ V, written into concat-head layout ----------------
__global__ __launch_bounds__(256) void attn_av_kernel(
    const float* __restrict__ sc, const float* __restrict__ v, float* __restrict__ oc)
{
    const int t0 = blockIdx.x * 64;
    const int bh = blockIdx.y;
    const int b = bh / HH, h = bh % HH;
    __shared__ float Ps[64][68];
    __shared__ float Vs[64][68];
    const int tid = threadIdx.x;
    const int tx = tid & 15, ty = tid >> 4;

    float acc[4][4];
#pragma unroll
    for (int i = 0; i < 4; i++)
#pragma unroll
        for (int j = 0; j < 4; j++) acc[i][j] = 0.f;

    const int ktmax = t0 / 64;   // causal: s <= t0+63
    for (int kt = 0; kt <= ktmax; kt++) {
#pragma unroll
        for (int ld = 0; ld < 4; ld++) {
            int f = tid + ld * 256;
            int row = f >> 4, c = (f & 15) << 2;
            *(float4*)&Ps[row][c] = *(const float4*)(sc + ((size_t)bh * TT + t0 + row) * TT + kt * 64 + c);
            *(float4*)&Vs[row][c] = *(const float4*)(v + (size_t)(b * TT + kt * 64 + row) * DD + h * HD + c);
        }
        __syncthreads();
#pragma unroll 4
        for (int ss = 0; ss < 64; ss++) {
            float a[4];
#pragma unroll
            for (int i = 0; i < 4; i++) a[i] = Ps[ty * 4 + i][ss];
            float4 bv = *(float4*)&Vs[ss][tx * 4];
            float bb[4] = {bv.x, bv.y, bv.z, bv.w};
#pragma unroll
            for (int i = 0; i < 4; i++)
#pragma unroll
                for (int j = 0; j < 4; j++)
                    acc[i][j] = fmaf(a[i], bb[j], acc[i][j]);
        }
        __syncthreads();
    }

#pragma unroll
    for (int i = 0; i < 4; i++) {
        size_t base = (size_t)(b * TT + t0 + ty * 4 + i) * DD + h * HD + tx * 4;
#pragma unroll
        for (int j = 0; j < 4; j++)
            oc[base + j] = acc[i][j];
    }
}

// ---------------- final LayerNorm ----------------
__global__ __launch_bounds__(256) void ln_kernel(
    const float* __restrict__ x, const float* __restrict__ g,
    const float* __restrict__ b, float* __restrict__ y)
{
    const int r = blockIdx.x;
    const int tid = threadIdx.x;
    const float* row = x + (size_t)r * DD;
    __shared__ float sh[256];

    float s = 0.f;
    for (int d = tid; d < DD; d += 256) s += row[d];
    sh[tid] = s; __syncthreads();
    for (int k = 128; k > 0; k >>= 1) { if (tid < k) sh[tid] += sh[tid + k]; __syncthreads(); }
    float mu = sh[0] / DD; __syncthreads();

    float vs = 0.f;
    for (int d = tid; d < DD; d += 256) { float t = row[d] - mu; vs += t * t; }
    sh[tid] = vs; __syncthreads();
    for (int k = 128; k > 0; k >>= 1) { if (tid < k) sh[tid] += sh[tid + k]; __syncthreads(); }
    float inv = rsqrtf(sh[0] / DD + EPS);

    float* out = y + (size_t)r * DD;
    for (int d = tid; d < DD; d += 256)
        out[d] = (row[d] - mu) * inv * g[d] + b[d];
}

// ---------------- per-row NLL from logits ----------------
__global__ __launch_bounds__(256) void loss_rows_kernel(
    const float* __restrict__ logits, const int* __restrict__ targets, float* __restrict__ nll)
{
    const int r = blockIdx.x;
    const int tid = threadIdx.x;
    const float* row = logits + (size_t)r * VV;
    __shared__ float sh[256];

    float m = -INFINITY;
    for (int i = tid; i < VV; i += 256) m = fmaxf(m, row[i]);
    sh[tid] = m; __syncthreads();
    for (int s = 128; s > 0; s >>= 1) { if (tid < s) sh[tid] = fmaxf(sh[tid], sh[tid + s]); __syncthreads(); }
    m = sh[0]; __syncthreads();

    float ssum = 0.f;
    for (int i = tid; i < VV; i += 256) ssum += expf(row[i] - m);
    sh[tid] = ssum; __syncthreads();
    for (int s = 128; s > 0; s >>= 1) { if (tid < s) sh[tid] += sh[tid + s]; __syncthreads(); }

    if (tid == 0)
        nll[r] = -(row[targets[r]] - m - logf(sh[0]));
}

__global__ __launch_bounds__(256) void loss_reduce_kernel(
    const float* __restrict__ nll, float* __restrict__ dst)
{
    const int tid = threadIdx.x;
    __shared__ float sh[256];
    float s = 0.f;
    for (int i = tid; i < MM; i += 256) s += nll[i];
    sh[tid] = s; __syncthreads();
    for (int k = 128; k > 0; k >>= 1) { if (tid < k) sh[tid] += sh[tid + k]; __syncthreads(); }
    if (tid == 0) dst[0] = sh[0] / (float)MM;
}

// ---------------- orchestration ----------------
extern "C" void kernel_launch(void* const* d_in, const int* in_sizes, int n_in,
                              void* d_out, int out_size)
{
    const int*   idx     = (const int*)  d_in[0];
    const int*   targets = (const int*)  d_in[1];
    const float* tok     = (const float*)d_in[2];
    const float* pos     = (const float*)d_in[3];
    const float* Wq      = (const float*)d_in[4];
    const float* Wk      = (const float*)d_in[5];
    const float* Wv      = (const float*)d_in[6];
    const float* Wo      = (const float*)d_in[7];
    const float* bo      = (const float*)d_in[8];
    const float* W1      = (const float*)d_in[9];
    const float* b1      = (const float*)d_in[10];
    const float* W2      = (const float*)d_in[11];
    const float* b2      = (const float*)d_in[12];
    const float* ln_g    = (const float*)d_in[13];
    const float* ln_b    = (const float*)d_in[14];
    const float* Wf      = (const float*)d_in[15];
    const float* bf      = (const float*)d_in[16];
    (void)in_sizes; (void)n_in;

    float *x, *x2, *q, *k, *v, *oc, *hbuf, *sc, *wt, *nll, *lscratch;
    cudaGetSymbolAddress((void**)&x,  g_x);
    cudaGetSymbolAddress((void**)&x2, g_x2);
    cudaGetSymbolAddress((void**)&q,  g_q);
    cudaGetSymbolAddress((void**)&k,  g_k);
    cudaGetSymbolAddress((void**)&v,  g_v);
    cudaGetSymbolAddress((void**)&oc, g_oc);
    cudaGetSymbolAddress((void**)&hbuf, g_h);
    cudaGetSymbolAddress((void**)&sc, g_sc);
    cudaGetSymbolAddress((void**)&wt, g_wt);
    cudaGetSymbolAddress((void**)&nll, g_nll);
    cudaGetSymbolAddress((void**)&lscratch, g_logits_scratch);

    float* out = (float*)d_out;
    const size_t LOGN = (size_t)MM * VV;
    float* logits = ((size_t)out_size >= LOGN) ? out : lscratch;
    float* loss_dst = nullptr;
    if ((size_t)out_size >= LOGN + 1)      loss_dst = out + LOGN;
    else if (out_size == 1)                loss_dst = out;

    // 1. embedding
    embed_kernel<<<(unsigned)(((size_t)MM * DD + 255) / 256), 256>>>(idx, tok, pos, x);

    // 2. repack qkv weights
    {
        size_t total = (size_t)LL * 3 * DD * DD;
        pack_qkv_kernel<<<(unsigned)((total + 255) / 256), 256>>>(Wq, Wk, Wv, wt);
    }

    // 3. transformer layers
    for (int l = 0; l < LL; l++) {
        const float* wq_l = wt + (size_t)(l * 3 + 0) * DD * DD;
        const float* wk_l = wt + (size_t)(l * 3 + 1) * DD * DD;
        const float* wv_l = wt + (size_t)(l * 3 + 2) * DD * DD;

        dim3 gD(DD / 128, MM / 128);
        gemm128<false,false,false><<<gD, 256>>>(x, wq_l, nullptr, nullptr, q, MM, DD, DD);
        gemm128<false,false,false><<<gD, 256>>>(x, wk_l, nullptr, nullptr, k, MM, DD, DD);
        gemm128<false,false,false><<<gD, 256>>>(x, wv_l, nullptr, nullptr, v, MM, DD, DD);

        attn_scores_kernel<<<dim3(TT / 64, TT / 64, BH), 256>>>(q, k, sc);
        softmax_kernel<<<dim3(TT, BH), 256>>>(sc);
        attn_av_kernel<<<dim3(TT / 64, BH), 256>>>(sc, v, oc);

        // x2 = x + oc @ Wo + bo
        gemm128<true,false,true><<<gD, 256>>>(oc, Wo + (size_t)l * DD * DD,
                                              bo + (size_t)l * DD, x, x2, MM, DD, DD);
        // h = relu(x2 @ W1 + b1)
        gemm128<true,true,false><<<dim3(FF / 128, MM / 128), 256>>>(
            x2, W1 + (size_t)l * DD * FF, b1 + (size_t)l * FF, nullptr, hbuf, MM, FF, DD);
        // x = x2 + h @ W2 + b2
        gemm128<true,false,true><<<gD, 256>>>(hbuf, W2 + (size_t)l * FF * DD,
                                              b2 + (size_t)l * DD, x2, x, MM, DD, FF);
    }

    // 4. final layernorm
    ln_kernel<<<MM, 256>>>(x, ln_g, ln_b, x2);

    // 5. logits = ln(x) @ Wf + bf
    gemm128<true,false,false><<<dim3(VV / 128, MM / 128), 256>>>(
        x2, Wf, bf, nullptr, logits, MM, VV, DD);

    // 6. loss
    if (loss_dst) {
        loss_rows_kernel<<<MM, 256>>>(logits, targets, nll);
        loss_reduce_kernel<<<1, 256>>>(nll, loss_dst);
    }
}

// round 9
// speedup vs baseline: 2.1086x; 2.1086x over previous
#include <cuda_runtime.h>
#include <cuda_bf16.h>
#include <math.h>
#include <stdint.h>

// ---------------- problem constants ----------------
#define BB 2
#define TT 1024
#define DD 1024
#define HH 16
#define HD 64
#define LL 6
#define VV 32000
#define FF 4096          // 4*D
#define MM (BB*TT)       // 2048 rows
#define BH (BB*HH)       // 32 (b,h) pairs
#define QKVD (3*DD)      // fused qkv row width
#define EPS 1e-5f
#define ATT_SCALE 0.03125f   // D^-0.5 = 1/32 (source scales by n_embd)

// ---------------- scratch (static device globals; no allocs) ----------------
__device__ float g_x   [(size_t)MM*DD];
__device__ float g_x2  [(size_t)MM*DD];
__device__ float g_qkv [(size_t)MM*QKVD];       // fused q|k|v, row stride 3072
__device__ float g_oc  [(size_t)MM*DD];
__device__ float g_h   [(size_t)MM*FF];
__device__ float g_sc  [(size_t)BH*TT*TT];      // 128 MB attention scores
__device__ float g_wt  [(size_t)LL*DD*QKVD];    // repacked Wq/Wk/Wv -> [L, D, 3*D]
__device__ float g_nll [MM];
__device__ float g_logits_scratch[(size_t)MM*VV];

// ---------------- embedding ----------------
__global__ __launch_bounds__(256) void embed_kernel(
    const int* __restrict__ idx, const float* __restrict__ tok,
    const float* __restrict__ pos, float* __restrict__ x)
{
    size_t i = (size_t)blockIdx.x * 256 + threadIdx.x;
    if (i >= (size_t)MM * DD) return;
    int d = (int)(i % DD);
    int r = (int)(i / DD);
    int t = r % TT;
    x[i] = tok[(size_t)idx[r] * DD + d] + pos[(size_t)t * DD + d];
}

// ---------------- repack Wq/Wk/Wv [L,H,D,HD] -> [L, D, 3*D] ----------------
// dest col layout: [0,D) = Q (h*HD+e), [D,2D) = K, [2D,3D) = V
__global__ __launch_bounds__(256) void pack_qkv_kernel(
    const float* __restrict__ Wq, const float* __restrict__ Wk,
    const float* __restrict__ Wv, float* __restrict__ wt)
{
    size_t i = (size_t)blockIdx.x * 256 + threadIdx.x;
    size_t total = (size_t)LL * 3 * DD * DD;
    if (i >= total) return;
    int e = (int)(i % HD); size_t r = i / HD;
    int d = (int)(r % DD); r /= DD;
    int h = (int)(r % HH); r /= HH;
    int m = (int)(r % 3);  int l = (int)(r / 3);
    const float* src = (m == 0) ? Wq : (m == 1) ? Wk : Wv;
    float val = src[(((size_t)l * HH + h) * DD + d) * HD + e];
    wt[((size_t)l * DD + d) * QKVD + (size_t)m * DD + (size_t)h * HD + e] = val;
}

// ---------------- tf32 tensor-core GEMM, 128x128x32 tiles ----------------
// C[M,N] = A[M,K] @ B[K,N] (+bias) (+resid) (relu); M%128==0, N%128==0, K%32==0.
__device__ __forceinline__ float cvt_tf32(float x) {
    uint32_t u;
    asm("cvt.rna.tf32.f32 %0, %1;" : "=r"(u) : "f"(x));
    return __uint_as_float(u);
}

template<bool BIAS, bool RELU, bool RESID>
__global__ __launch_bounds__(256, 2) void gemm_tf32(
    const float* __restrict__ A, const float* __restrict__ Bm,
    const float* __restrict__ bias, const float* __restrict__ resid,
    float* __restrict__ C, int M, int N, int K)
{
    __shared__ __align__(16) float As[128][36];   // [m][k], pad 36: frag bank = lane
    __shared__ __align__(16) float Bs[32][136];   // [k][n], pad 136: frag bank = 8*tig+gid

    const int tid  = threadIdx.x;
    const int wid  = tid >> 5, lane = tid & 31;
    const int wm   = wid & 1;          // 0..1 : warp row (64 rows each)
    const int wn   = wid >> 1;         // 0..3 : warp col (32 cols each)
    const int gid  = lane >> 2;        // groupID 0..7
    const int tig  = lane & 3;         // threadID-in-group 0..3
    const int m0   = blockIdx.y * 128, n0 = blockIdx.x * 128;

    float acc[4][4][4];
#pragma unroll
    for (int i = 0; i < 4; i++)
#pragma unroll
        for (int j = 0; j < 4; j++)
#pragma unroll
            for (int r = 0; r < 4; r++) acc[i][j][r] = 0.f;

    for (int kk = 0; kk < K; kk += 32) {
        // --- load A tile 128x32 (coalesced float4, tf32-rounded) ---
#pragma unroll
        for (int it = 0; it < 4; it++) {
            int f   = tid + it * 256;
            int row = f >> 3, c4 = (f & 7) << 2;
            float4 v = *(const float4*)(A + (size_t)(m0 + row) * K + kk + c4);
            float4 w = make_float4(cvt_tf32(v.x), cvt_tf32(v.y), cvt_tf32(v.z), cvt_tf32(v.w));
            *(float4*)&As[row][c4] = w;
        }
        // --- load B tile 32x128 (coalesced float4, tf32-rounded) ---
#pragma unroll
        for (int it = 0; it < 4; it++) {
            int f   = tid + it * 256;
            int row = f >> 5, c4 = (f & 31) << 2;
            float4 v = *(const float4*)(Bm + (size_t)(kk + row) * N + n0 + c4);
            float4 w = make_float4(cvt_tf32(v.x), cvt_tf32(v.y), cvt_tf32(v.z), cvt_tf32(v.w));
            *(float4*)&Bs[row][c4] = w;
        }
        __syncthreads();

#pragma unroll
        for (int ks = 0; ks < 4; ks++) {
            const int k0 = ks * 8;
            uint32_t af[4][4];
#pragma unroll
            for (int i = 0; i < 4; i++) {
                int r = wm * 64 + i * 16;
                af[i][0] = __float_as_uint(As[r + gid    ][k0 + tig    ]);
                af[i][1] = __float_as_uint(As[r + gid + 8][k0 + tig    ]);
                af[i][2] = __float_as_uint(As[r + gid    ][k0 + tig + 4]);
                af[i][3] = __float_as_uint(As[r + gid + 8][k0 + tig + 4]);
            }
            uint32_t bf[4][2];
#pragma unroll
            for (int j = 0; j < 4; j++) {
                int c = wn * 32 + j * 8;
                bf[j][0] = __float_as_uint(Bs[k0 + tig    ][c + gid]);
                bf[j][1] = __float_as_uint(Bs[k0 + tig + 4][c + gid]);
            }
#pragma unroll
            for (int i = 0; i < 4; i++)
#pragma unroll
                for (int j = 0; j < 4; j++) {
                    asm volatile(
                        "mma.sync.aligned.m16n8k8.row.col.f32.tf32.tf32.f32 "
                        "{%0,%1,%2,%3}, {%4,%5,%6,%7}, {%8,%9}, {%0,%1,%2,%3};\n"
                        : "+f"(acc[i][j][0]), "+f"(acc[i][j][1]),
                          "+f"(acc[i][j][2]), "+f"(acc[i][j][3])
                        : "r"(af[i][0]), "r"(af[i][1]), "r"(af[i][2]), "r"(af[i][3]),
                          "r"(bf[j][0]), "r"(bf[j][1]));
                }
        }
        __syncthreads();
    }

    // --- epilogue: c0/c1 at (row, col/col+1); c2/c3 at (row+8, col/col+1) ---
#pragma unroll
    for (int i = 0; i < 4; i++) {
        int r0 = m0 + wm * 64 + i * 16 + gid;
#pragma unroll
        for (int j = 0; j < 4; j++) {
            int c0 = n0 + wn * 32 + j * 8 + 2 * tig;
            float v00 = acc[i][j][0], v01 = acc[i][j][1];
            float v10 = acc[i][j][2], v11 = acc[i][j][3];
            if (BIAS) {
                float b0v = bias[c0], b1v = bias[c0 + 1];
                v00 += b0v; v01 += b1v; v10 += b0v; v11 += b1v;
            }
            size_t base0 = (size_t)r0 * N + c0;
            size_t base1 = (size_t)(r0 + 8) * N + c0;
            if (RESID) {
                v00 += resid[base0]; v01 += resid[base0 + 1];
                v10 += resid[base1]; v11 += resid[base1 + 1];
            }
            if (RELU) {
                v00 = fmaxf(v00, 0.f); v01 = fmaxf(v01, 0.f);
                v10 = fmaxf(v10, 0.f); v11 = fmaxf(v11, 0.f);
            }
            C[base0] = v00; C[base0 + 1] = v01;
            C[base1] = v10; C[base1 + 1] = v11;
        }
    }
}

// ---------------- attention: scores = scale * Q K^T (lower-triangular blocks) ----------------
// q/k live in fused qkv buffer with row stride QKVD; k at col offset DD.
__global__ __launch_bounds__(256) void attn_scores_kernel(
    const float* __restrict__ qkv, float* __restrict__ sc)
{
    const int bh = blockIdx.z;
    const int b = bh / HH, h = bh % HH;
    const int t0 = blockIdx.y * 64, s0 = blockIdx.x * 64;
    if (s0 > t0 + 63) return;
    __shared__ float Qs[64][68];
    __shared__ float Ks[64][68];
    const int tid = threadIdx.x;
    const int tx = tid & 15, ty = tid >> 4;

#pragma unroll
    for (int ld = 0; ld < 4; ld++) {
        int f = tid + ld * 256;
        int row = f >> 4, c = (f & 15) << 2;
        *(float4*)&Qs[row][c] = *(const float4*)(qkv + (size_t)(b * TT + t0 + row) * QKVD + h * HD + c);
        *(float4*)&Ks[row][c] = *(const float4*)(qkv + (size_t)(b * TT + s0 + row) * QKVD + DD + h * HD + c);
    }
    __syncthreads();

    float acc[4][4];
#pragma unroll
    for (int i = 0; i < 4; i++)
#pragma unroll
        for (int j = 0; j < 4; j++) acc[i][j] = 0.f;

#pragma unroll 4
    for (int e = 0; e < 64; e++) {
        float a[4], bb[4];
#pragma unroll
        for (int i = 0; i < 4; i++) a[i]  = Qs[ty * 4 + i][e];
#pragma unroll
        for (int j = 0; j < 4; j++) bb[j] = Ks[tx * 4 + j][e];
#pragma unroll
        for (int i = 0; i < 4; i++)
#pragma unroll
            for (int j = 0; j < 4; j++)
                acc[i][j] = fmaf(a[i], bb[j], acc[i][j]);
    }

#pragma unroll
    for (int i = 0; i < 4; i++) {
        size_t base = ((size_t)bh * TT + t0 + ty * 4 + i) * TT + s0 + tx * 4;
#pragma unroll
        for (int j = 0; j < 4; j++)
            sc[base + j] = acc[i][j] * ATT_SCALE;
    }
}

// ---------------- causal row softmax ----------------
__global__ __launch_bounds__(256) void softmax_kernel(float* __restrict__ sc)
{
    const int t = blockIdx.x, bh = blockIdx.y;
    float* row = sc + ((size_t)bh * TT + t) * TT;
    const int n = t + 1;
    const int tid = threadIdx.x;
    __shared__ float sh[256];

    float m = -INFINITY;
    for (int i = tid; i < n; i += 256) m = fmaxf(m, row[i]);
    sh[tid] = m; __syncthreads();
    for (int s = 128; s > 0; s >>= 1) { if (tid < s) sh[tid] = fmaxf(sh[tid], sh[tid + s]); __syncthreads(); }
    m = sh[0]; __syncthreads();

    float ssum = 0.f;
    for (int i = tid; i < n; i += 256) {
        float e = expf(row[i] - m);
        row[i] = e;
        ssum += e;
    }
    sh[tid] = ssum; __syncthreads();
    for (int s = 128; s > 0; s >>= 1) { if (tid < s) sh[tid] += sh[tid + s]; __syncthreads(); }
    float inv = 1.f / sh[0]; __syncthreads();

    for (int i = tid; i < TT; i += 256) {
        if (i < n) row[i] *= inv;
        else       row[i] = 0.f;
    }
}

// ---------------- O = att @ V (v in fused qkv at col offset 2*DD) ----------------
__global__ __launch_bounds__(256) void attn_av_kernel(
    const float* __restrict__ sc, const float* __restrict__ qkv, float* __restrict__ oc)
{
    const int t0 = blockIdx.x * 64;
    const int bh = blockIdx.y;
    const int b = bh / HH, h = bh % HH;
    __shared__ float Ps[64][68];
    __shared__ float Vs[64][68];
    const int tid = threadIdx.x;
    const int tx = tid & 15, ty = tid >> 4;

    float acc[4][4];
#pragma unroll
    for (int i = 0; i < 4; i++)
#pragma unroll
        for (int j = 0; j < 4; j++) acc[i][j] = 0.f;

    const int ktmax = t0 / 64;
    for (int kt = 0; kt <= ktmax; kt++) {
#pragma unroll
        for (int ld = 0; ld < 4; ld++) {
            int f = tid + ld * 256;
            int row = f >> 4, c = (f & 15) << 2;
            *(float4*)&Ps[row][c] = *(const float4*)(sc + ((size_t)bh * TT + t0 + row) * TT + kt * 64 + c);
            *(float4*)&Vs[row][c] = *(const float4*)(qkv + (size_t)(b * TT + kt * 64 + row) * QKVD + 2 * DD + h * HD + c);
        }
        __syncthreads();
#pragma unroll 4
        for (int ss = 0; ss < 64; ss++) {
            float a[4];
#pragma unroll
            for (int i = 0; i < 4; i++) a[i] = Ps[ty * 4 + i][ss];
            float4 bv = *(float4*)&Vs[ss][tx * 4];
            float bb[4] = {bv.x, bv.y, bv.z, bv.w};
#pragma unroll
            for (int i = 0; i < 4; i++)
#pragma unroll
                for (int j = 0; j < 4; j++)
                    acc[i][j] = fmaf(a[i], bb[j], acc[i][j]);
        }
        __syncthreads();
    }

#pragma unroll
    for (int i = 0; i < 4; i++) {
        size_t base = (size_t)(b * TT + t0 + ty * 4 + i) * DD + h * HD + tx * 4;
#pragma unroll
        for (int j = 0; j < 4; j++)
            oc[base + j] = acc[i][j];
    }
}

// ---------------- final LayerNorm ----------------
__global__ __launch_bounds__(256) void ln_kernel(
    const float* __restrict__ x, const float* __restrict__ g,
    const float* __restrict__ b, float* __restrict__ y)
{
    const int r = blockIdx.x;
    const int tid = threadIdx.x;
    const float* row = x + (size_t)r * DD;
    __shared__ float sh[256];

    float s = 0.f;
    for (int d = tid; d < DD; d += 256) s += row[d];
    sh[tid] = s; __syncthreads();
    for (int k = 128; k > 0; k >>= 1) { if (tid < k) sh[tid] += sh[tid + k]; __syncthreads(); }
    float mu = sh[0] / DD; __syncthreads();

    float vs = 0.f;
    for (int d = tid; d < DD; d += 256) { float t = row[d] - mu; vs += t * t; }
    sh[tid] = vs; __syncthreads();
    for (int k = 128; k > 0; k >>= 1) { if (tid < k) sh[tid] += sh[tid + k]; __syncthreads(); }
    float inv = rsqrtf(sh[0] / DD + EPS);

    float* out = y + (size_t)r * DD;
    for (int d = tid; d < DD; d += 256)
        out[d] = (row[d] - mu) * inv * g[d] + b[d];
}

// ---------------- per-row NLL from logits ----------------
__global__ __launch_bounds__(256) void loss_rows_kernel(
    const float* __restrict__ logits, const int* __restrict__ targets, float* __restrict__ nll)
{
    const int r = blockIdx.x;
    const int tid = threadIdx.x;
    const float* row = logits + (size_t)r * VV;
    __shared__ float sh[256];

    float m = -INFINITY;
    for (int i = tid; i < VV; i += 256) m = fmaxf(m, row[i]);
    sh[tid] = m; __syncthreads();
    for (int s = 128; s > 0; s >>= 1) { if (tid < s) sh[tid] = fmaxf(sh[tid], sh[tid + s]); __syncthreads(); }
    m = sh[0]; __syncthreads();

    float ssum = 0.f;
    for (int i = tid; i < VV; i += 256) ssum += expf(row[i] - m);
    sh[tid] = ssum; __syncthreads();
    for (int s = 128; s > 0; s >>= 1) { if (tid < s) sh[tid] += sh[tid + s]; __syncthreads(); }

    if (tid == 0)
        nll[r] = -(row[targets[r]] - m - logf(sh[0]));
}

__global__ __launch_bounds__(256) void loss_reduce_kernel(
    const float* __restrict__ nll, float* __restrict__ dst)
{
    const int tid = threadIdx.x;
    __shared__ float sh[256];
    float s = 0.f;
    for (int i = tid; i < MM; i += 256) s += nll[i];
    sh[tid] = s; __syncthreads();
    for (int k = 128; k > 0; k >>= 1) { if (tid < k) sh[tid] += sh[tid + k]; __syncthreads(); }
    if (tid == 0) dst[0] = sh[0] / (float)MM;
}

// ---------------- orchestration ----------------
extern "C" void kernel_launch(void* const* d_in, const int* in_sizes, int n_in,
                              void* d_out, int out_size)
{
    const int*   idx     = (const int*)  d_in[0];
    const int*   targets = (const int*)  d_in[1];
    const float* tok     = (const float*)d_in[2];
    const float* pos     = (const float*)d_in[3];
    const float* Wq      = (const float*)d_in[4];
    const float* Wk      = (const float*)d_in[5];
    const float* Wv      = (const float*)d_in[6];
    const float* Wo      = (const float*)d_in[7];
    const float* bo      = (const float*)d_in[8];
    const float* W1      = (const float*)d_in[9];
    const float* b1      = (const float*)d_in[10];
    const float* W2      = (const float*)d_in[11];
    const float* b2      = (const float*)d_in[12];
    const float* ln_g    = (const float*)d_in[13];
    const float* ln_b    = (const float*)d_in[14];
    const float* Wf      = (const float*)d_in[15];
    const float* bf      = (const float*)d_in[16];
    (void)in_sizes; (void)n_in;

    float *x, *x2, *qkv, *oc, *hbuf, *sc, *wt, *nll, *lscratch;
    cudaGetSymbolAddress((void**)&x,   g_x);
    cudaGetSymbolAddress((void**)&x2,  g_x2);
    cudaGetSymbolAddress((void**)&qkv, g_qkv);
    cudaGetSymbolAddress((void**)&oc,  g_oc);
    cudaGetSymbolAddress((void**)&hbuf, g_h);
    cudaGetSymbolAddress((void**)&sc,  g_sc);
    cudaGetSymbolAddress((void**)&wt,  g_wt);
    cudaGetSymbolAddress((void**)&nll, g_nll);
    cudaGetSymbolAddress((void**)&lscratch, g_logits_scratch);

    float* out = (float*)d_out;
    const size_t LOGN = (size_t)MM * VV;
    float* logits = ((size_t)out_size >= LOGN) ? out : lscratch;
    float* loss_dst = nullptr;
    if ((size_t)out_size >= LOGN + 1)      loss_dst = out + LOGN;
    else if (out_size == 1)                loss_dst = out;

    // 1. embedding
    embed_kernel<<<(unsigned)(((size_t)MM * DD + 255) / 256), 256>>>(idx, tok, pos, x);

    // 2. repack qkv weights into [L, D, 3*D]
    {
        size_t total = (size_t)LL * 3 * DD * DD;
        pack_qkv_kernel<<<(unsigned)((total + 255) / 256), 256>>>(Wq, Wk, Wv, wt);
    }

    // 3. transformer layers
    for (int l = 0; l < LL; l++) {
        const float* wqkv_l = wt + (size_t)l * DD * QKVD;

        // fused qkv = x @ Wqkv   [2048 x 3072]
        gemm_tf32<false,false,false><<<dim3(QKVD / 128, MM / 128), 256>>>(
            x, wqkv_l, nullptr, nullptr, qkv, MM, QKVD, DD);

        attn_scores_kernel<<<dim3(TT / 64, TT / 64, BH), 256>>>(qkv, sc);
        softmax_kernel<<<dim3(TT, BH), 256>>>(sc);
        attn_av_kernel<<<dim3(TT / 64, BH), 256>>>(sc, qkv, oc);

        dim3 gD(DD / 128, MM / 128);
        // x2 = x + oc @ Wo + bo
        gemm_tf32<true,false,true><<<gD, 256>>>(oc, Wo + (size_t)l * DD * DD,
                                                bo + (size_t)l * DD, x, x2, MM, DD, DD);
        // h = relu(x2 @ W1 + b1)
        gemm_tf32<true,true,false><<<dim3(FF / 128, MM / 128), 256>>>(
            x2, W1 + (size_t)l * DD * FF, b1 + (size_t)l * FF, nullptr, hbuf, MM, FF, DD);
        // x = x2 + h @ W2 + b2
        gemm_tf32<true,false,true><<<gD, 256>>>(hbuf, W2 + (size_t)l * FF * DD,
                                                b2 + (size_t)l * DD, x2, x, MM, DD, FF);
    }

    // 4. final layernorm
    ln_kernel<<<MM, 256>>>(x, ln_g, ln_b, x2);

    // 5. logits = ln(x) @ Wf + bf
    gemm_tf32<true,false,false><<<dim3(VV / 128, MM / 128), 256>>>(
        x2, Wf, bf, nullptr, logits, MM, VV, DD);

    // 6. loss
    if (loss_dst) {
        loss_rows_kernel<<<MM, 256>>>(logits, targets, nll);
        loss_reduce_kernel<<<1, 256>>>(nll, loss_dst);
    }
}

// round 12
// speedup vs baseline: 2.2401x; 1.0624x over previous
#include <cuda_runtime.h>
#include <cuda_bf16.h>
#include <math.h>
#include <stdint.h>

// ---------------- problem constants ----------------
#define BB 2
#define TT 1024
#define DD 1024
#define HH 16
#define HD 64
#define LL 6
#define VV 32000
#define FF 4096          // 4*D
#define MM (BB*TT)       // 2048 rows
#define BH (BB*HH)       // 32 (b,h) pairs
#define QKVD (3*DD)      // fused qkv row width
#define EPS 1e-5f
#define ATT_SCALE 0.03125f   // D^-0.5 = 1/32 (source scales by n_embd)

// ---------------- scratch (static device globals; no allocs) ----------------
__device__ float g_x   [(size_t)MM*DD];
__device__ float g_x2  [(size_t)MM*DD];
__device__ float g_qkv [(size_t)MM*QKVD];       // fused q|k|v, row stride 3072
__device__ float g_oc  [(size_t)MM*DD];
__device__ float g_h   [(size_t)MM*FF];
__device__ float g_sc  [(size_t)BH*TT*TT];      // 128 MB attention scores
__device__ float g_wt  [(size_t)LL*DD*QKVD];    // repacked Wq/Wk/Wv -> [L, D, 3*D]
__device__ float g_nll [MM];
__device__ float g_logits_scratch[(size_t)MM*VV];

// ---------------- embedding ----------------
__global__ __launch_bounds__(256) void embed_kernel(
    const int* __restrict__ idx, const float* __restrict__ tok,
    const float* __restrict__ pos, float* __restrict__ x)
{
    size_t i = (size_t)blockIdx.x * 256 + threadIdx.x;
    if (i >= (size_t)MM * DD) return;
    int d = (int)(i % DD);
    int r = (int)(i / DD);
    int t = r % TT;
    x[i] = tok[(size_t)idx[r] * DD + d] + pos[(size_t)t * DD + d];
}

// ---------------- repack Wq/Wk/Wv [L,H,D,HD] -> [L, D, 3*D] ----------------
__global__ __launch_bounds__(256) void pack_qkv_kernel(
    const float* __restrict__ Wq, const float* __restrict__ Wk,
    const float* __restrict__ Wv, float* __restrict__ wt)
{
    size_t i = (size_t)blockIdx.x * 256 + threadIdx.x;
    size_t total = (size_t)LL * 3 * DD * DD;
    if (i >= total) return;
    int e = (int)(i % HD); size_t r = i / HD;
    int d = (int)(r % DD); r /= DD;
    int h = (int)(r % HH); r /= HH;
    int m = (int)(r % 3);  int l = (int)(r / 3);
    const float* src = (m == 0) ? Wq : (m == 1) ? Wk : Wv;
    float val = src[(((size_t)l * HH + h) * DD + d) * HD + e];
    wt[((size_t)l * DD + d) * QKVD + (size_t)m * DD + (size_t)h * HD + e] = val;
}

// ---------------- tf32 tensor-core GEMM, 128x128x32 tiles (unchanged from R9) ----------------
__device__ __forceinline__ float cvt_tf32(float x) {
    uint32_t u;
    asm("cvt.rna.tf32.f32 %0, %1;" : "=r"(u) : "f"(x));
    return __uint_as_float(u);
}

template<bool BIAS, bool RELU, bool RESID>
__global__ __launch_bounds__(256, 2) void gemm_tf32(
    const float* __restrict__ A, const float* __restrict__ Bm,
    const float* __restrict__ bias, const float* __restrict__ resid,
    float* __restrict__ C, int M, int N, int K)
{
    __shared__ __align__(16) float As[128][36];
    __shared__ __align__(16) float Bs[32][136];

    const int tid  = threadIdx.x;
    const int wid  = tid >> 5, lane = tid & 31;
    const int wm   = wid & 1;
    const int wn   = wid >> 1;
    const int gid  = lane >> 2;
    const int tig  = lane & 3;
    const int m0   = blockIdx.y * 128, n0 = blockIdx.x * 128;

    float acc[4][4][4];
#pragma unroll
    for (int i = 0; i < 4; i++)
#pragma unroll
        for (int j = 0; j < 4; j++)
#pragma unroll
            for (int r = 0; r < 4; r++) acc[i][j][r] = 0.f;

    for (int kk = 0; kk < K; kk += 32) {
#pragma unroll
        for (int it = 0; it < 4; it++) {
            int f   = tid + it * 256;
            int row = f >> 3, c4 = (f & 7) << 2;
            float4 v = *(const float4*)(A + (size_t)(m0 + row) * K + kk + c4);
            float4 w = make_float4(cvt_tf32(v.x), cvt_tf32(v.y), cvt_tf32(v.z), cvt_tf32(v.w));
            *(float4*)&As[row][c4] = w;
        }
#pragma unroll
        for (int it = 0; it < 4; it++) {
            int f   = tid + it * 256;
            int row = f >> 5, c4 = (f & 31) << 2;
            float4 v = *(const float4*)(Bm + (size_t)(kk + row) * N + n0 + c4);
            float4 w = make_float4(cvt_tf32(v.x), cvt_tf32(v.y), cvt_tf32(v.z), cvt_tf32(v.w));
            *(float4*)&Bs[row][c4] = w;
        }
        __syncthreads();

#pragma unroll
        for (int ks = 0; ks < 4; ks++) {
            const int k0 = ks * 8;
            uint32_t af[4][4];
#pragma unroll
            for (int i = 0; i < 4; i++) {
                int r = wm * 64 + i * 16;
                af[i][0] = __float_as_uint(As[r + gid    ][k0 + tig    ]);
                af[i][1] = __float_as_uint(As[r + gid + 8][k0 + tig    ]);
                af[i][2] = __float_as_uint(As[r + gid    ][k0 + tig + 4]);
                af[i][3] = __float_as_uint(As[r + gid + 8][k0 + tig + 4]);
            }
            uint32_t bf[4][2];
#pragma unroll
            for (int j = 0; j < 4; j++) {
                int c = wn * 32 + j * 8;
                bf[j][0] = __float_as_uint(Bs[k0 + tig    ][c + gid]);
                bf[j][1] = __float_as_uint(Bs[k0 + tig + 4][c + gid]);
            }
#pragma unroll
            for (int i = 0; i < 4; i++)
#pragma unroll
                for (int j = 0; j < 4; j++) {
                    asm volatile(
                        "mma.sync.aligned.m16n8k8.row.col.f32.tf32.tf32.f32 "
                        "{%0,%1,%2,%3}, {%4,%5,%6,%7}, {%8,%9}, {%0,%1,%2,%3};\n"
                        : "+f"(acc[i][j][0]), "+f"(acc[i][j][1]),
                          "+f"(acc[i][j][2]), "+f"(acc[i][j][3])
                        : "r"(af[i][0]), "r"(af[i][1]), "r"(af[i][2]), "r"(af[i][3]),
                          "r"(bf[j][0]), "r"(bf[j][1]));
                }
        }
        __syncthreads();
    }

#pragma unroll
    for (int i = 0; i < 4; i++) {
        int r0 = m0 + wm * 64 + i * 16 + gid;
#pragma unroll
        for (int j = 0; j < 4; j++) {
            int c0 = n0 + wn * 32 + j * 8 + 2 * tig;
            float v00 = acc[i][j][0], v01 = acc[i][j][1];
            float v10 = acc[i][j][2], v11 = acc[i][j][3];
            if (BIAS) {
                float b0v = bias[c0], b1v = bias[c0 + 1];
                v00 += b0v; v01 += b1v; v10 += b0v; v11 += b1v;
            }
            size_t base0 = (size_t)r0 * N + c0;
            size_t base1 = (size_t)(r0 + 8) * N + c0;
            if (RESID) {
                v00 += resid[base0]; v01 += resid[base0 + 1];
                v10 += resid[base1]; v11 += resid[base1 + 1];
            }
            if (RELU) {
                v00 = fmaxf(v00, 0.f); v01 = fmaxf(v01, 0.f);
                v10 = fmaxf(v10, 0.f); v11 = fmaxf(v11, 0.f);
            }
            C[base0] = v00; C[base0 + 1] = v01;
            C[base1] = v10; C[base1 + 1] = v11;
        }
    }
}

// ---------------- attention scores v2: 64x64 tile, 64 threads, 8x8/thread ----------------
// smem stored TRANSPOSED [e][row] so fragments load as float4 -> 16 FMA / LDS.128.
__global__ __launch_bounds__(64) void attn_scores_kernel(
    const float* __restrict__ qkv, float* __restrict__ sc)
{
    const int bh = blockIdx.z;
    const int b = bh / HH, h = bh % HH;
    const int t0 = blockIdx.y * 64, s0 = blockIdx.x * 64;
    if (s0 > t0) return;                 // fully masked block
    __shared__ float QsT[64][68];        // [e][t]
    __shared__ float KsT[64][68];        // [e][s]
    const int tid = threadIdx.x;
    const int tx = tid & 7, ty = tid >> 3;

#pragma unroll
    for (int it = 0; it < 16; it++) {
        int f   = tid + it * 64;             // 1024 float4 per tile
        int row = f >> 4, c4 = (f & 15) << 2;
        float4 q  = *(const float4*)(qkv + (size_t)(b * TT + t0 + row) * QKVD + h * HD + c4);
        float4 kv = *(const float4*)(qkv + (size_t)(b * TT + s0 + row) * QKVD + DD + h * HD + c4);
        QsT[c4 + 0][row] = q.x;  QsT[c4 + 1][row] = q.y;
        QsT[c4 + 2][row] = q.z;  QsT[c4 + 3][row] = q.w;
        KsT[c4 + 0][row] = kv.x; KsT[c4 + 1][row] = kv.y;
        KsT[c4 + 2][row] = kv.z; KsT[c4 + 3][row] = kv.w;
    }
    __syncthreads();

    float acc[8][8];
#pragma unroll
    for (int i = 0; i < 8; i++)
#pragma unroll
        for (int j = 0; j < 8; j++) acc[i][j] = 0.f;

#pragma unroll 4
    for (int e = 0; e < 64; e++) {
        float4 a0 = *(float4*)&QsT[e][ty * 8];
        float4 a1 = *(float4*)&QsT[e][ty * 8 + 4];
        float4 b0 = *(float4*)&KsT[e][tx * 8];
        float4 b1 = *(float4*)&KsT[e][tx * 8 + 4];
        float a[8] = {a0.x,a0.y,a0.z,a0.w,a1.x,a1.y,a1.z,a1.w};
        float bb[8] = {b0.x,b0.y,b0.z,b0.w,b1.x,b1.y,b1.z,b1.w};
#pragma unroll
        for (int i = 0; i < 8; i++)
#pragma unroll
            for (int j = 0; j < 8; j++)
                acc[i][j] = fmaf(a[i], bb[j], acc[i][j]);
    }

#pragma unroll
    for (int i = 0; i < 8; i++) {
        size_t base = ((size_t)bh * TT + t0 + ty * 8 + i) * TT + s0 + tx * 8;
        float4 o0 = make_float4(acc[i][0]*ATT_SCALE, acc[i][1]*ATT_SCALE,
                                acc[i][2]*ATT_SCALE, acc[i][3]*ATT_SCALE);
        float4 o1 = make_float4(acc[i][4]*ATT_SCALE, acc[i][5]*ATT_SCALE,
                                acc[i][6]*ATT_SCALE, acc[i][7]*ATT_SCALE);
        *(float4*)(sc + base)     = o0;
        *(float4*)(sc + base + 4) = o1;
    }
}

// ---------------- causal softmax v2: register-resident row (1 read + 1 write) ----------------
__global__ __launch_bounds__(256) void softmax_kernel(float* __restrict__ sc)
{
    const int t = blockIdx.x, bh = blockIdx.y;
    float* row = sc + ((size_t)bh * TT + t) * TT;
    const int tid = threadIdx.x;
    const int lane = tid & 31, wid = tid >> 5;
    const int c0 = tid * 4;
    __shared__ float sm[8];

    float4 v = *(float4*)(row + c0);
    float vv[4] = {v.x, v.y, v.z, v.w};

    float m = -INFINITY;
#pragma unroll
    for (int k = 0; k < 4; k++)
        if (c0 + k <= t) m = fmaxf(m, vv[k]);
#pragma unroll
    for (int off = 16; off > 0; off >>= 1)
        m = fmaxf(m, __shfl_xor_sync(0xffffffffu, m, off));
    if (lane == 0) sm[wid] = m;
    __syncthreads();
    float bm = -INFINITY;
#pragma unroll
    for (int w = 0; w < 8; w++) bm = fmaxf(bm, sm[w]);
    __syncthreads();

    float s = 0.f;
#pragma unroll
    for (int k = 0; k < 4; k++) {
        vv[k] = (c0 + k <= t) ? expf(vv[k] - bm) : 0.f;
        s += vv[k];
    }
#pragma unroll
    for (int off = 16; off > 0; off >>= 1)
        s += __shfl_xor_sync(0xffffffffu, s, off);
    if (lane == 0) sm[wid] = s;
    __syncthreads();
    float stot = 0.f;
#pragma unroll
    for (int w = 0; w < 8; w++) stot += sm[w];
    float inv = 1.f / stot;

    *(float4*)(row + c0) = make_float4(vv[0]*inv, vv[1]*inv, vv[2]*inv, vv[3]*inv);
}

// ---------------- O = att @ V v2: 64x64 tile, 64 threads, 8x8/thread ----------------
__global__ __launch_bounds__(64) void attn_av_kernel(
    const float* __restrict__ sc, const float* __restrict__ qkv, float* __restrict__ oc)
{
    const int t0 = blockIdx.x * 64;
    const int bh = blockIdx.y;
    const int b = bh / HH, h = bh % HH;
    __shared__ float PsT[64][68];   // [s][t]
    __shared__ float Vs [64][68];   // [s][e]
    const int tid = threadIdx.x;
    const int tx = tid & 7, ty = tid >> 3;

    float acc[8][8];
#pragma unroll
    for (int i = 0; i < 8; i++)
#pragma unroll
        for (int j = 0; j < 8; j++) acc[i][j] = 0.f;

    const int ktmax = t0 / 64;      // causal: s <= t0+63
    for (int kt = 0; kt <= ktmax; kt++) {
#pragma unroll
        for (int it = 0; it < 16; it++) {
            int f   = tid + it * 64;
            int row = f >> 4, c4 = (f & 15) << 2;
            float4 p  = *(const float4*)(sc + ((size_t)bh * TT + t0 + row) * TT + kt * 64 + c4);
            PsT[c4 + 0][row] = p.x; PsT[c4 + 1][row] = p.y;
            PsT[c4 + 2][row] = p.z; PsT[c4 + 3][row] = p.w;
            float4 vv = *(const float4*)(qkv + (size_t)(b * TT + kt * 64 + row) * QKVD + 2 * DD + h * HD + c4);
            *(float4*)&Vs[row][c4] = vv;
        }
        __syncthreads();

#pragma unroll 4
        for (int ss = 0; ss < 64; ss++) {
            float4 a0 = *(float4*)&PsT[ss][ty * 8];
            float4 a1 = *(float4*)&PsT[ss][ty * 8 + 4];
            float4 b0 = *(float4*)&Vs[ss][tx * 8];
            float4 b1 = *(float4*)&Vs[ss][tx * 8 + 4];
            float a[8] = {a0.x,a0.y,a0.z,a0.w,a1.x,a1.y,a1.z,a1.w};
            float bb[8] = {b0.x,b0.y,b0.z,b0.w,b1.x,b1.y,b1.z,b1.w};
#pragma unroll
            for (int i = 0; i < 8; i++)
#pragma unroll
                for (int j = 0; j < 8; j++)
                    acc[i][j] = fmaf(a[i], bb[j], acc[i][j]);
        }
        __syncthreads();
    }

#pragma unroll
    for (int i = 0; i < 8; i++) {
        size_t base = (size_t)(b * TT + t0 + ty * 8 + i) * DD + h * HD + tx * 8;
        *(float4*)(oc + base)     = make_float4(acc[i][0], acc[i][1], acc[i][2], acc[i][3]);
        *(float4*)(oc + base + 4) = make_float4(acc[i][4], acc[i][5], acc[i][6], acc[i][7]);
    }
}

// ---------------- final LayerNorm ----------------
__global__ __launch_bounds__(256) void ln_kernel(
    const float* __restrict__ x, const float* __restrict__ g,
    const float* __restrict__ b, float* __restrict__ y)
{
    const int r = blockIdx.x;
    const int tid = threadIdx.x;
    const float* row = x + (size_t)r * DD;
    __shared__ float sh[256];

    float s = 0.f;
    for (int d = tid; d < DD; d += 256) s += row[d];
    sh[tid] = s; __syncthreads();
    for (int k = 128; k > 0; k >>= 1) { if (tid < k) sh[tid] += sh[tid + k]; __syncthreads(); }
    float mu = sh[0] / DD; __syncthreads();

    float vs = 0.f;
    for (int d = tid; d < DD; d += 256) { float t = row[d] - mu; vs += t * t; }
    sh[tid] = vs; __syncthreads();
    for (int k = 128; k > 0; k >>= 1) { if (tid < k) sh[tid] += sh[tid + k]; __syncthreads(); }
    float inv = rsqrtf(sh[0] / DD + EPS);

    float* out = y + (size_t)r * DD;
    for (int d = tid; d < DD; d += 256)
        out[d] = (row[d] - mu) * inv * g[d] + b[d];
}

// ---------------- per-row NLL from logits ----------------
__global__ __launch_bounds__(256) void loss_rows_kernel(
    const float* __restrict__ logits, const int* __restrict__ targets, float* __restrict__ nll)
{
    const int r = blockIdx.x;
    const int tid = threadIdx.x;
    const float* row = logits + (size_t)r * VV;
    __shared__ float sh[256];

    float m = -INFINITY;
    for (int i = tid; i < VV; i += 256) m = fmaxf(m, row[i]);
    sh[tid] = m; __syncthreads();
    for (int s = 128; s > 0; s >>= 1) { if (tid < s) sh[tid] = fmaxf(sh[tid], sh[tid + s]); __syncthreads(); }
    m = sh[0]; __syncthreads();

    float ssum = 0.f;
    for (int i = tid; i < VV; i += 256) ssum += expf(row[i] - m);
    sh[tid] = ssum; __syncthreads();
    for (int s = 128; s > 0; s >>= 1) { if (tid < s) sh[tid] += sh[tid + s]; __syncthreads(); }

    if (tid == 0)
        nll[r] = -(row[targets[r]] - m - logf(sh[0]));
}

__global__ __launch_bounds__(256) void loss_reduce_kernel(
    const float* __restrict__ nll, float* __restrict__ dst)
{
    const int tid = threadIdx.x;
    __shared__ float sh[256];
    float s = 0.f;
    for (int i = tid; i < MM; i += 256) s += nll[i];
    sh[tid] = s; __syncthreads();
    for (int k = 128; k > 0; k >>= 1) { if (tid < k) sh[tid] += sh[tid + k]; __syncthreads(); }
    if (tid == 0) dst[0] = sh[0] / (float)MM;
}

// ---------------- orchestration ----------------
extern "C" void kernel_launch(void* const* d_in, const int* in_sizes, int n_in,
                              void* d_out, int out_size)
{
    const int*   idx     = (const int*)  d_in[0];
    const int*   targets = (const int*)  d_in[1];
    const float* tok     = (const float*)d_in[2];
    const float* pos     = (const float*)d_in[3];
    const float* Wq      = (const float*)d_in[4];
    const float* Wk      = (const float*)d_in[5];
    const float* Wv      = (const float*)d_in[6];
    const float* Wo      = (const float*)d_in[7];
    const float* bo      = (const float*)d_in[8];
    const float* W1      = (const float*)d_in[9];
    const float* b1      = (const float*)d_in[10];
    const float* W2      = (const float*)d_in[11];
    const float* b2      = (const float*)d_in[12];
    const float* ln_g    = (const float*)d_in[13];
    const float* ln_b    = (const float*)d_in[14];
    const float* Wf      = (const float*)d_in[15];
    const float* bf      = (const float*)d_in[16];
    (void)in_sizes; (void)n_in;

    float *x, *x2, *qkv, *oc, *hbuf, *sc, *wt, *nll, *lscratch;
    cudaGetSymbolAddress((void**)&x,   g_x);
    cudaGetSymbolAddress((void**)&x2,  g_x2);
    cudaGetSymbolAddress((void**)&qkv, g_qkv);
    cudaGetSymbolAddress((void**)&oc,  g_oc);
    cudaGetSymbolAddress((void**)&hbuf, g_h);
    cudaGetSymbolAddress((void**)&sc,  g_sc);
    cudaGetSymbolAddress((void**)&wt,  g_wt);
    cudaGetSymbolAddress((void**)&nll, g_nll);
    cudaGetSymbolAddress((void**)&lscratch, g_logits_scratch);

    float* out = (float*)d_out;
    const size_t LOGN = (size_t)MM * VV;
    float* logits = ((size_t)out_size >= LOGN) ? out : lscratch;
    float* loss_dst = nullptr;
    if ((size_t)out_size >= LOGN + 1)      loss_dst = out + LOGN;
    else if (out_size == 1)                loss_dst = out;

    // 1. embedding
    embed_kernel<<<(unsigned)(((size_t)MM * DD + 255) / 256), 256>>>(idx, tok, pos, x);

    // 2. repack qkv weights into [L, D, 3*D]
    {
        size_t total = (size_t)LL * 3 * DD * DD;
        pack_qkv_kernel<<<(unsigned)((total + 255) / 256), 256>>>(Wq, Wk, Wv, wt);
    }

    // 3. transformer layers
    for (int l = 0; l < LL; l++) {
        const float* wqkv_l = wt + (size_t)l * DD * QKVD;

        // fused qkv = x @ Wqkv   [2048 x 3072]
        gemm_tf32<false,false,false><<<dim3(QKVD / 128, MM / 128), 256>>>(
            x, wqkv_l, nullptr, nullptr, qkv, MM, QKVD, DD);

        attn_scores_kernel<<<dim3(TT / 64, TT / 64, BH), 64>>>(qkv, sc);
        softmax_kernel<<<dim3(TT, BH), 256>>>(sc);
        attn_av_kernel<<<dim3(TT / 64, BH), 64>>>(sc, qkv, oc);

        dim3 gD(DD / 128, MM / 128);
        // x2 = x + oc @ Wo + bo
        gemm_tf32<true,false,true><<<gD, 256>>>(oc, Wo + (size_t)l * DD * DD,
                                                bo + (size_t)l * DD, x, x2, MM, DD, DD);
        // h = relu(x2 @ W1 + b1)
        gemm_tf32<true,true,false><<<dim3(FF / 128, MM / 128), 256>>>(
            x2, W1 + (size_t)l * DD * FF, b1 + (size_t)l * FF, nullptr, hbuf, MM, FF, DD);
        // x = x2 + h @ W2 + b2
        gemm_tf32<true,false,true><<<gD, 256>>>(hbuf, W2 + (size_t)l * FF * DD,
                                                b2 + (size_t)l * DD, x2, x, MM, DD, FF);
    }

    // 4. final layernorm
    ln_kernel<<<MM, 256>>>(x, ln_g, ln_b, x2);

    // 5. logits = ln(x) @ Wf + bf
    gemm_tf32<true,false,false><<<dim3(VV / 128, MM / 128), 256>>>(
        x2, Wf, bf, nullptr, logits, MM, VV, DD);

    // 6. loss
    if (loss_dst) {
        loss_rows_kernel<<<MM, 256>>>(logits, targets, nll);
        loss_reduce_kernel<<<1, 256>>>(nll, loss_dst);
    }
}